// round 9
// baseline (speedup 1.0000x reference)
#include <cuda_runtime.h>

// out[i,j,k] = C[i,j,k] * x[i,j]
// B=4096, INPUT_SIZE=512, EMBED_DIM=64 -> n = 2^27 floats, n8 = 2^24 float8
//
// v9: 256-bit global loads/stores (Blackwell LDG.256/STG.256 via PTX v8.f32).
// Same winning geometry as R6/R8 (512 threads, 64KB block tiles): 4 x float8
// per thread. .nc loads on C, .cs stores on out, __ldg on x (L2-resident).

#define THREADS 512
#define UNROLL  4   // float8 groups per thread -> 4*32B = 128B/thread

__device__ __forceinline__ void ldg256_nc(const float* p, float* r) {
    asm volatile(
        "ld.global.nc.v8.f32 {%0,%1,%2,%3,%4,%5,%6,%7}, [%8];"
        : "=f"(r[0]), "=f"(r[1]), "=f"(r[2]), "=f"(r[3]),
          "=f"(r[4]), "=f"(r[5]), "=f"(r[6]), "=f"(r[7])
        : "l"(p));
}

__device__ __forceinline__ void stg256_cs(float* p, const float* r) {
    asm volatile(
        "st.global.cs.v8.f32 [%0], {%1,%2,%3,%4,%5,%6,%7,%8};"
        :: "l"(p),
           "f"(r[0]), "f"(r[1]), "f"(r[2]), "f"(r[3]),
           "f"(r[4]), "f"(r[5]), "f"(r[6]), "f"(r[7])
        : "memory");
}

__global__ __launch_bounds__(THREADS)
void bcast_mul_exact(const float* __restrict__ x,
                     const float* __restrict__ C,
                     float* __restrict__ out) {
    const unsigned base = blockIdx.x * (THREADS * UNROLL) + threadIdx.x;  // float8 units

    float c[UNROLL][8];
    float s[UNROLL];
#pragma unroll
    for (int j = 0; j < UNROLL; j++) {
        unsigned i8 = base + j * THREADS;
        ldg256_nc(C + ((size_t)i8 << 3), c[j]);
        s[j] = __ldg(&x[i8 >> 3]);         // 8 float8-groups per x scalar
    }
#pragma unroll
    for (int j = 0; j < UNROLL; j++) {
        unsigned i8 = base + j * THREADS;
        float o[8];
#pragma unroll
        for (int k = 0; k < 8; k++) o[k] = c[j][k] * s[j];
        stg256_cs(out + ((size_t)i8 << 3), o);
    }
}

__global__ void bcast_mul_generic(const float* __restrict__ x,
                                  const float4* __restrict__ C4,
                                  float4* __restrict__ out4,
                                  unsigned n4) {
    unsigned i = blockIdx.x * blockDim.x + threadIdx.x;
    if (i < n4) {
        float s = __ldg(&x[i >> 4]);
        float4 c = __ldcs(&C4[i]);
        float4 o;
        o.x = c.x * s; o.y = c.y * s; o.z = c.z * s; o.w = c.w * s;
        __stcs(&out4[i], o);
    }
}

extern "C" void kernel_launch(void* const* d_in, const int* in_sizes, int n_in,
                              void* d_out, int out_size) {
    const float* x;
    const float* C;
    if (in_sizes[0] < in_sizes[1]) {
        x = (const float*)d_in[0];
        C = (const float*)d_in[1];
    } else {
        x = (const float*)d_in[1];
        C = (const float*)d_in[0];
    }

    long long n = (long long)out_size;                 // 134,217,728
    unsigned n8 = (unsigned)(n >> 3);                  // 16,777,216 float8
    const unsigned per_block = THREADS * UNROLL;       // 2048 float8 = 64KB

    if (n8 % per_block == 0) {
        bcast_mul_exact<<<n8 / per_block, THREADS>>>(x, C, (float*)d_out);
    } else {
        unsigned n4 = (unsigned)(n >> 2);
        bcast_mul_generic<<<(n4 + 255) / 256, 256>>>(
            x, (const float4*)C, (float4*)d_out, n4);
    }
}

// round 10
// speedup vs baseline: 1.0120x; 1.0120x over previous
#include <cuda_runtime.h>

// out[i,j,k] = C[i,j,k] * x[i,j]
// B=4096, INPUT_SIZE=512, EMBED_DIM=64 -> n = 2^27 floats, n4 = 2^25 float4
//
// FINAL kernel — best measured wall time (157.1us R6, 157.9us R8 repro),
// 6.75 TB/s = 85% of HBM spec on provably-minimal traffic (1.032 GB).
//
//  - 512 threads x 8 unroll, block-contiguous 4096-float4 (64KB r + 64KB w) tiles
//  - exact-division fast kernel, zero predication; generic fallback for safety
//  - __ldcs on C (read-once), __stcs on out (beats __stwt, tested R7),
//    __ldg on x (L2-resident, 64x reuse)
//
// Search exhausted R1-R9: vector width {128b,256b}, MLP {1,4,8,16},
// threads {256,512}, tiling {grid-stride, block-contiguous}, store {cs,wt},
// occupancy {32-79%} — all plateau at 6.67-6.78 TB/s. In-kernel time is
// pinned at 151.4-153.7us across every config; the binding resource is
// achieved HBM bandwidth on a mixed read/write stream, not anything SM-side.

#define THREADS 512
#define UNROLL  8

__global__ __launch_bounds__(THREADS)
void bcast_mul_exact(const float* __restrict__ x,
                     const float4* __restrict__ C4,
                     float4* __restrict__ out4) {
    const unsigned base = blockIdx.x * (THREADS * UNROLL) + threadIdx.x;

    float4 c[UNROLL];
    float  s[UNROLL];
#pragma unroll
    for (int j = 0; j < UNROLL; j++) {
        unsigned i = base + j * THREADS;
        c[j] = __ldcs(&C4[i]);
        s[j] = __ldg(&x[i >> 4]);          // 16 float4-groups per x scalar
    }
#pragma unroll
    for (int j = 0; j < UNROLL; j++) {
        unsigned i = base + j * THREADS;
        float4 o;
        o.x = c[j].x * s[j];
        o.y = c[j].y * s[j];
        o.z = c[j].z * s[j];
        o.w = c[j].w * s[j];
        __stcs(&out4[i], o);
    }
}

__global__ void bcast_mul_generic(const float* __restrict__ x,
                                  const float4* __restrict__ C4,
                                  float4* __restrict__ out4,
                                  unsigned n4) {
    unsigned i = blockIdx.x * blockDim.x + threadIdx.x;
    if (i < n4) {
        float s = __ldg(&x[i >> 4]);
        float4 c = __ldcs(&C4[i]);
        float4 o;
        o.x = c.x * s; o.y = c.y * s; o.z = c.z * s; o.w = c.w * s;
        __stcs(&out4[i], o);
    }
}

extern "C" void kernel_launch(void* const* d_in, const int* in_sizes, int n_in,
                              void* d_out, int out_size) {
    const float* x;
    const float* C;
    if (in_sizes[0] < in_sizes[1]) {
        x = (const float*)d_in[0];
        C = (const float*)d_in[1];
    } else {
        x = (const float*)d_in[1];
        C = (const float*)d_in[0];
    }

    unsigned n4 = (unsigned)((long long)out_size >> 2);   // 33,554,432
    const unsigned per_block = THREADS * UNROLL;          // 4096

    if (n4 % per_block == 0) {
        bcast_mul_exact<<<n4 / per_block, THREADS>>>(
            x, (const float4*)C, (float4*)d_out);
    } else {
        bcast_mul_generic<<<(n4 + 255) / 256, 256>>>(
            x, (const float4*)C, (float4*)d_out, n4);
    }
}